// round 3
// baseline (speedup 1.0000x reference)
#include <cuda_runtime.h>
#include <math.h>

#define BATCH 16
#define CH    3
#define H     512
#define W     512
#define WS    11
#define PAD   5

#define TX    64
#define TY    32
#define TXH   76            // TX + 2*PAD, padded to mult of 4
#define TYH   (TY + 2*PAD)  // 42
#define NTHREADS 256
#define NBLK  ((W/TX)*(H/TY)*BATCH)   // 2048

typedef unsigned long long u64;

struct GW { float w[WS]; };

__device__ float    g_pnum[NBLK];
__device__ float    g_pden[NBLK];
__device__ unsigned g_cnt;   // zero-init; last block resets to 0 each call

// ---------------- f32x2 packed helpers (sm_103a FFMA2 path) ----------------
__device__ __forceinline__ u64 pk2(float lo, float hi) {
    u64 r; asm("mov.b64 %0, {%1, %2};" : "=l"(r) : "f"(lo), "f"(hi)); return r;
}
__device__ __forceinline__ float lo2(u64 v) {
    float a, b; asm("mov.b64 {%0, %1}, %2;" : "=f"(a), "=f"(b) : "l"(v)); return a;
}
__device__ __forceinline__ float hi2(u64 v) {
    float a, b; asm("mov.b64 {%0, %1}, %2;" : "=f"(a), "=f"(b) : "l"(v)); return b;
}
__device__ __forceinline__ u64 mul2(u64 a, u64 b) {
    u64 d; asm("mul.rn.f32x2 %0, %1, %2;" : "=l"(d) : "l"(a), "l"(b)); return d;
}
__device__ __forceinline__ u64 add2(u64 a, u64 b) {
    u64 d; asm("add.rn.f32x2 %0, %1, %2;" : "=l"(d) : "l"(a), "l"(b)); return d;
}
__device__ __forceinline__ u64 fma2(u64 a, u64 b, u64 c) {
    u64 d; asm("fma.rn.f32x2 %0, %1, %2, %3;" : "=l"(d) : "l"(a), "l"(b), "l"(c)); return d;
}

extern __shared__ float smem[];

// smem layout (floats):
//   raw   : 2*TYH*TXH = 6384   interleaved (v1,v2) float2 per pixel
//   hM    : 2*TYH*TX  = 5376   (mu1h, mu2h) float2
//   hE    : 2*TYH*TX  = 5376   (E11h, E22h) float2
//   hE12  :   TYH*TX  = 2688   E12h scalar (also reused as mask hbox scratch)
//   maskb :   TY*TX   = 2048
#define OFF_RAW   0
#define OFF_HM    (2*TYH*TXH)
#define OFF_HE    (OFF_HM + 2*TYH*TX)
#define OFF_HE12  (OFF_HE + 2*TYH*TX)
#define OFF_MASK  (OFF_HE12 + TYH*TX)
#define SMEM_FLOATS (OFF_MASK + TY*TX)
#define SMEM_BYTES  (SMEM_FLOATS * (int)sizeof(float))

__global__ __launch_bounds__(NTHREADS, 2) void ssim_kernel(
    const float* __restrict__ img1,
    const float* __restrict__ img2,
    const float* __restrict__ match,
    float* __restrict__ out,
    GW gw)
{
    float* raw   = smem + OFF_RAW;
    float* hM    = smem + OFF_HM;
    float* hE    = smem + OFF_HE;
    float* hE12  = smem + OFF_HE12;
    float* maskb = smem + OFF_MASK;

    const int tid = threadIdx.x;
    const int x0 = blockIdx.x * TX;
    const int y0 = blockIdx.y * TY;
    const int b  = blockIdx.z;

    float lnum = 0.f;
    float lden = 0.f;

    // ======================= mask pass (box filter on match) =======================
    {
        const float* mp = match + (size_t)b * H * W;
        for (int i = tid; i < TYH * TXH; i += NTHREADS) {
            int y = i / TXH, x = i - y * TXH;
            int gy = y0 + y - PAD, gx = x0 + x - PAD;
            float v = 0.f;
            if ((unsigned)gy < H && (unsigned)gx < W) v = mp[gy * W + gx];
            raw[i] = v;
        }
        __syncthreads();
        // horizontal box (vectorized, 4 outputs/thread)
        for (int i = tid; i < TYH * (TX / 4); i += NTHREADS) {
            int xg = i & 15;
            int y  = i >> 4;
            const float4* rp = (const float4*)(raw + y * TXH) + xg;
            float v[16];
            #pragma unroll
            for (int q = 0; q < 4; q++) {
                float4 t = rp[q];
                v[4*q+0]=t.x; v[4*q+1]=t.y; v[4*q+2]=t.z; v[4*q+3]=t.w;
            }
            float s[4] = {0,0,0,0};
            #pragma unroll
            for (int k = 0; k < WS; k++) {
                #pragma unroll
                for (int r = 0; r < 4; r++) s[r] += v[k + r];
            }
            *(float4*)(hE12 + y * TX + xg * 4) = make_float4(s[0], s[1], s[2], s[3]);
        }
        __syncthreads();
        // vertical box + threshold (vectorized)
        for (int i = tid; i < TY * (TX / 4); i += NTHREADS) {
            int xg = i & 15;
            int y  = i >> 4;
            float s[4] = {0,0,0,0};
            #pragma unroll
            for (int k = 0; k < WS; k++) {
                float4 t = *(const float4*)(hE12 + (y + k) * TX + xg * 4);
                s[0] += t.x; s[1] += t.y; s[2] += t.z; s[3] += t.w;
            }
            float mv[4];
            #pragma unroll
            for (int r = 0; r < 4; r++) {
                float m = s[r] * (1.0f / 121.0f) + 1e-07f;
                mv[r] = (m > 0.5f) ? (1.0f + 1e-07f) : 1e-07f;
                lden += mv[r];
            }
            *(float4*)(maskb + y * TX + xg * 4) = make_float4(mv[0], mv[1], mv[2], mv[3]);
        }
        __syncthreads();
    }

    // ======================= per-channel SSIM =======================
    for (int c = 0; c < CH; c++) {
        const float* p1 = img1 + ((size_t)b * CH + c) * H * W;
        const float* p2 = img2 + ((size_t)b * CH + c) * H * W;

        // load halo tiles, interleaved (v1,v2)
        for (int i = tid; i < TYH * TXH; i += NTHREADS) {
            int y = i / TXH, x = i - y * TXH;
            int gy = y0 + y - PAD, gx = x0 + x - PAD;
            float v1 = 0.f, v2 = 0.f;
            if ((unsigned)gy < H && (unsigned)gx < W) {
                int gi = gy * W + gx;
                v1 = p1[gi];
                v2 = p2[gi];
            }
            *(float2*)(raw + 2 * i) = make_float2(v1, v2);
        }
        __syncthreads();

        // -------- horizontal Gaussian pass: packed f32x2, 4 outputs/thread
        for (int i = tid; i < TYH * (TX / 4); i += NTHREADS) {
            int xg = i & 15;
            int y  = i >> 4;
            const ulonglong2* rp =
                (const ulonglong2*)(raw + (size_t)(y * TXH + xg * 4) * 2);
            u64 v[16];
            #pragma unroll
            for (int q = 0; q < 8; q++) {
                ulonglong2 t = rp[q];
                v[2*q] = t.x; v[2*q+1] = t.y;
            }
            u64 M12[4]  = {0,0,0,0};
            u64 E1122[4]= {0,0,0,0};
            float E12[4]= {0,0,0,0};
            #pragma unroll
            for (int k = 0; k < WS; k++) {
                u64 ww = pk2(gw.w[k], gw.w[k]);
                #pragma unroll
                for (int r = 0; r < 4; r++) {
                    u64 wb = mul2(ww, v[k + r]);                 // (w*v1, w*v2)
                    M12[r]   = add2(M12[r], wb);                 // (mu1, mu2)
                    E1122[r] = fma2(wb, v[k + r], E1122[r]);     // (E11, E22)
                    E12[r]   = fmaf(lo2(wb), hi2(v[k + r]), E12[r]); // w*v1*v2
                }
            }
            int o = y * TX + xg * 4;
            ulonglong2* sm = (ulonglong2*)(hM + 2 * o);
            sm[0] = make_ulonglong2(M12[0], M12[1]);
            sm[1] = make_ulonglong2(M12[2], M12[3]);
            ulonglong2* se = (ulonglong2*)(hE + 2 * o);
            se[0] = make_ulonglong2(E1122[0], E1122[1]);
            se[1] = make_ulonglong2(E1122[2], E1122[3]);
            *(float4*)(hE12 + o) = make_float4(E12[0], E12[1], E12[2], E12[3]);
        }
        __syncthreads();

        // -------- vertical Gaussian + SSIM: 4 x-lanes, 2 y-outputs per thread
        {
            int i = tid;                 // exactly (TY/2)*(TX/4) = 256 items
            int xg = i & 15;
            int yb = (i >> 4) * 2;
            u64 VM[2][4], VE[2][4], V12[2][2];
            #pragma unroll
            for (int r = 0; r < 2; r++) {
                #pragma unroll
                for (int j = 0; j < 4; j++) { VM[r][j] = 0; VE[r][j] = 0; }
                V12[r][0] = 0; V12[r][1] = 0;
            }
            #pragma unroll
            for (int k = 0; k < WS + 1; k++) {      // 12 rows serve 2 outputs
                int row = yb + k;
                int o = row * TX + xg * 4;
                ulonglong2 m01 = ((const ulonglong2*)(hM + 2 * o))[0];
                ulonglong2 m23 = ((const ulonglong2*)(hM + 2 * o))[1];
                ulonglong2 e01 = ((const ulonglong2*)(hE + 2 * o))[0];
                ulonglong2 e23 = ((const ulonglong2*)(hE + 2 * o))[1];
                float4 ev = *(const float4*)(hE12 + o);
                u64 ea = pk2(ev.x, ev.y);
                u64 eb = pk2(ev.z, ev.w);
                #pragma unroll
                for (int r = 0; r < 2; r++) {
                    int kk = k - r;
                    if (kk >= 0 && kk < WS) {
                        u64 ww = pk2(gw.w[kk], gw.w[kk]);
                        VM[r][0] = fma2(ww, m01.x, VM[r][0]);
                        VM[r][1] = fma2(ww, m01.y, VM[r][1]);
                        VM[r][2] = fma2(ww, m23.x, VM[r][2]);
                        VM[r][3] = fma2(ww, m23.y, VM[r][3]);
                        VE[r][0] = fma2(ww, e01.x, VE[r][0]);
                        VE[r][1] = fma2(ww, e01.y, VE[r][1]);
                        VE[r][2] = fma2(ww, e23.x, VE[r][2]);
                        VE[r][3] = fma2(ww, e23.y, VE[r][3]);
                        V12[r][0] = fma2(ww, ea, V12[r][0]);
                        V12[r][1] = fma2(ww, eb, V12[r][1]);
                    }
                }
            }
            const float C1 = 1e-4f;
            const float C2 = 9e-4f;
            #pragma unroll
            for (int r = 0; r < 2; r++) {
                #pragma unroll
                for (int j = 0; j < 4; j++) {
                    float mu1 = lo2(VM[r][j]);
                    float mu2 = hi2(VM[r][j]);
                    float e11 = lo2(VE[r][j]);
                    float e22 = hi2(VE[r][j]);
                    float e12 = (j & 1) ? hi2(V12[r][j >> 1]) : lo2(V12[r][j >> 1]);
                    float mu1sq = mu1 * mu1;
                    float mu2sq = mu2 * mu2;
                    float mu12  = mu1 * mu2;
                    float s11 = e11 - mu1sq;
                    float s22 = e22 - mu2sq;
                    float s12 = e12 - mu12;
                    float numer = (2.f * mu12 + C1) * (2.f * s12 + C2);
                    float denom = (mu1sq + mu2sq + C1) * (s11 + s22 + C2);
                    float ssim = __fdividef(numer, denom);
                    lnum += (1.f - ssim) * maskb[(yb + r) * TX + xg * 4 + j];
                }
            }
        }
        __syncthreads();
    }

    // ======================= block reduction + partials + last-block finalize ====
    const unsigned full = 0xffffffffu;
    #pragma unroll
    for (int o = 16; o > 0; o >>= 1) {
        lnum += __shfl_down_sync(full, lnum, o);
        lden += __shfl_down_sync(full, lden, o);
    }
    __shared__ float red[16];
    __shared__ unsigned s_last;
    int wid = tid >> 5, lane = tid & 31;
    if (lane == 0) { red[wid] = lnum; red[wid + 8] = lden; }
    __syncthreads();
    if (tid == 0) {
        float n = 0.f, d = 0.f;
        #pragma unroll
        for (int i = 0; i < 8; i++) { n += red[i]; d += red[i + 8]; }
        int blk = (blockIdx.z * gridDim.y + blockIdx.y) * gridDim.x + blockIdx.x;
        g_pnum[blk] = n;
        g_pden[blk] = d;
        __threadfence();
        unsigned o = atomicAdd(&g_cnt, 1u);
        s_last = (o == NBLK - 1) ? 1u : 0u;
    }
    __syncthreads();

    if (s_last) {
        __threadfence();
        double dn = 0.0, dd = 0.0;
        for (int i = tid; i < NBLK; i += NTHREADS) {
            dn += (double)g_pnum[i];
            dd += (double)g_pden[i];
        }
        #pragma unroll
        for (int o = 16; o > 0; o >>= 1) {
            dn += __shfl_down_sync(full, dn, o);
            dd += __shfl_down_sync(full, dd, o);
        }
        __shared__ double dred[16];
        if (lane == 0) { dred[wid] = dn; dred[wid + 8] = dd; }
        __syncthreads();
        if (tid == 0) {
            double n = 0.0, d = 0.0;
            #pragma unroll
            for (int i = 0; i < 8; i++) { n += dred[i]; d += dred[i + 8]; }
            out[0] = (float)(n / d / 3.0);
            g_cnt = 0;   // reset for next graph replay
        }
    }
}

static GW make_weights() {
    GW g;
    double gg[WS], s = 0.0;
    for (int i = 0; i < WS; i++) {
        double d = (double)i - (double)(WS / 2);
        gg[i] = exp(-(d * d) / (2.0 * 1.5 * 1.5));
        s += gg[i];
    }
    for (int i = 0; i < WS; i++) g.w[i] = (float)(gg[i] / s);
    return g;
}

extern "C" void kernel_launch(void* const* d_in, const int* in_sizes, int n_in,
                              void* d_out, int out_size) {
    const float* img1  = (const float*)d_in[0];
    const float* img2  = (const float*)d_in[1];
    const float* match = (const float*)d_in[2];

    GW gw = make_weights();

    cudaFuncSetAttribute(ssim_kernel,
                         cudaFuncAttributeMaxDynamicSharedMemorySize, SMEM_BYTES);

    dim3 grid(W / TX, H / TY, BATCH);
    ssim_kernel<<<grid, NTHREADS, SMEM_BYTES>>>(img1, img2, match,
                                                (float*)d_out, gw);
}

// round 4
// speedup vs baseline: 1.8058x; 1.8058x over previous
#include <cuda_runtime.h>
#include <math.h>

#define BATCH 16
#define CH    3
#define H     512
#define W     512
#define WS    11

#define TX    64
#define TY    32
#define TXW   (TX + 10)     // 74 plane columns (x halo for horizontal pass)
#define XPAD  80            // padded x iteration range for pass V
#define PITCH 75            // odd pitch (u64 for vM/vE, float for v12/vbox) -> conflict-free
#define NTHREADS 256
#define NBLK  ((W/TX)*(H/TY)*BATCH)   // 2048

typedef unsigned long long u64;

// Gaussian weights (ws=11, sigma=1.5), normalized — compile-time literals
__device__ __constant__ const float GWC_dummy = 0.f; // (not used; keep constants as literals)
#define W0 0.00102838f
#define W1 0.00759876f
#define W2 0.03600077f
#define W3 0.10936070f
#define W4 0.21300554f
#define W5 0.26601173f
__device__ __forceinline__ float gwc(int k) {
    const float t[WS] = {W0,W1,W2,W3,W4,W5,W4,W3,W2,W1,W0};
    return t[k];   // fully-unrolled callers -> compile-time constant
}

__device__ float    g_pnum[NBLK];
__device__ float    g_pden[NBLK];
__device__ unsigned g_cnt;

// ---------------- f32x2 packed helpers ----------------
__device__ __forceinline__ u64 pk2(float lo, float hi) {
    u64 r; asm("mov.b64 %0, {%1, %2};" : "=l"(r) : "f"(lo), "f"(hi)); return r;
}
__device__ __forceinline__ float lo2(u64 v) {
    float a, b; asm("mov.b64 {%0, %1}, %2;" : "=f"(a), "=f"(b) : "l"(v)); return a;
}
__device__ __forceinline__ float hi2(u64 v) {
    float a, b; asm("mov.b64 {%0, %1}, %2;" : "=f"(a), "=f"(b) : "l"(v)); return b;
}
__device__ __forceinline__ u64 mul2(u64 a, u64 b) {
    u64 d; asm("mul.rn.f32x2 %0, %1, %2;" : "=l"(d) : "l"(a), "l"(b)); return d;
}
__device__ __forceinline__ u64 add2(u64 a, u64 b) {
    u64 d; asm("add.rn.f32x2 %0, %1, %2;" : "=l"(d) : "l"(a), "l"(b)); return d;
}
__device__ __forceinline__ u64 fma2(u64 a, u64 b, u64 c) {
    u64 d; asm("fma.rn.f32x2 %0, %1, %2, %3;" : "=l"(d) : "l"(a), "l"(b), "l"(c)); return d;
}

extern __shared__ float smem[];

// smem layout (floats):
//   vM   : TY*PITCH u64 = 4800 floats   packed (mu1v, mu2v)
//   vE   : TY*PITCH u64 = 4800 floats   packed (E11v, E22v)
//   v12  : TY*PITCH     = 2400 floats   E12v
//   vbox : TY*PITCH     = 2400 floats   vertical box sum of match
#define OFF_VM    0
#define OFF_VE    (TY*PITCH*2)
#define OFF_V12   (OFF_VE + TY*PITCH*2)
#define OFF_VBOX  (OFF_V12 + TY*PITCH)
#define SMEM_FLOATS (OFF_VBOX + TY*PITCH)
#define SMEM_BYTES  (SMEM_FLOATS * (int)sizeof(float))

__global__ __launch_bounds__(NTHREADS, 3) void ssim_kernel(
    const float* __restrict__ img1,
    const float* __restrict__ img2,
    const float* __restrict__ match,
    float* __restrict__ out)
{
    u64*   vM   = (u64*)(smem + OFF_VM);
    u64*   vE   = (u64*)(smem + OFF_VE);
    float* v12  = smem + OFF_V12;
    float* vbox = smem + OFF_VBOX;

    const int tid = threadIdx.x;
    const int x0 = blockIdx.x * TX;
    const int y0 = blockIdx.y * TY;
    const int b  = blockIdx.z;

    float lnum = 0.f;
    float lden = 0.f;
    float msk[2][4];   // mask per (H-pass iteration, r), computed at c==0

    // =================== pass V-box: vertical box sum of match ===================
    {
        const float* mp = match + (size_t)b * H * W;
        for (int i = tid; i < XPAD * (TY / 4); i += NTHREADS) {
            int x  = i % XPAD;
            int yb = (i / XPAD) * 4;
            if (x >= TXW) continue;
            int gx = x0 + x - 5;
            bool xin = (unsigned)gx < W;
            float S[4] = {0, 0, 0, 0};
            #pragma unroll
            for (int k = 0; k < WS + 3; k++) {
                int gy = y0 + yb + k - 5;
                float v = 0.f;
                if (xin && (unsigned)gy < H) v = mp[gy * W + gx];
                #pragma unroll
                for (int r = 0; r < 4; r++) {
                    int kk = k - r;
                    if (kk >= 0 && kk < WS) S[r] += v;
                }
            }
            #pragma unroll
            for (int r = 0; r < 4; r++) vbox[(yb + r) * PITCH + x] = S[r];
        }
        __syncthreads();
    }

    // =================== per-channel: pass V then pass H ===================
    for (int c = 0; c < CH; c++) {
        const float* p1 = img1 + ((size_t)b * CH + c) * H * W;
        const float* p2 = img2 + ((size_t)b * CH + c) * H * W;

        // ---- pass V: vertical Gaussian on raw moments, GMEM -> smem planes
        for (int i = tid; i < XPAD * (TY / 4); i += NTHREADS) {
            int x  = i % XPAD;
            int yb = (i / XPAD) * 4;
            if (x >= TXW) continue;
            int gx = x0 + x - 5;
            bool xin = (unsigned)gx < W;

            u64 VM[4] = {0,0,0,0};
            u64 VE[4] = {0,0,0,0};
            float V12[4] = {0,0,0,0};

            #pragma unroll
            for (int k = 0; k < WS + 3; k++) {
                int gy = y0 + yb + k - 5;
                float a = 0.f, bb = 0.f;
                if (xin && (unsigned)gy < H) {
                    int gi = gy * W + gx;
                    a  = p1[gi];
                    bb = p2[gi];
                }
                u64 v = pk2(a, bb);
                #pragma unroll
                for (int r = 0; r < 4; r++) {
                    int kk = k - r;
                    if (kk >= 0 && kk < WS) {
                        float w = gwc(kk);
                        u64 ww = pk2(w, w);
                        u64 wb = mul2(ww, v);         // (w*a, w*b)
                        VM[r] = add2(VM[r], wb);      // (mu1v, mu2v)
                        VE[r] = fma2(wb, v, VE[r]);   // (E11v, E22v)
                        V12[r] = fmaf(lo2(wb), bb, V12[r]);
                    }
                }
            }
            #pragma unroll
            for (int r = 0; r < 4; r++) {
                int o = (yb + r) * PITCH + x;
                vM[o]  = VM[r];
                vE[o]  = VE[r];
                v12[o] = V12[r];
            }
        }
        __syncthreads();

        // ---- pass H: horizontal Gaussian + SSIM. lanes = y (conflict-free odd pitch)
        #pragma unroll
        for (int ii = 0; ii < 2; ii++) {
            int i  = tid + ii * NTHREADS;      // 512 items total
            int y  = i & 31;
            int xg = i >> 5;
            int base = y * PITCH;              // u64 index for vM/vE, float for v12/vbox
            int cb = 4 * xg;

            // mask (channel 0 only): box horizontal sums from vbox
            if (c == 0) {
                float tb[WS + 3];
                #pragma unroll
                for (int k = 0; k < WS + 3; k++) tb[k] = vbox[base + cb + k];
                float S = 0.f;
                #pragma unroll
                for (int k = 0; k < WS; k++) S += tb[k];
                #pragma unroll
                for (int r = 0; r < 4; r++) {
                    if (r > 0) S = S - tb[r - 1] + tb[r + WS - 1];
                    float m = S * (1.0f / 121.0f) + 1e-07f;
                    float mv = (m > 0.5f) ? (1.0f + 1e-07f) : 1e-07f;
                    msk[ii][r] = mv;
                    lden += mv;
                }
            }

            u64 HM[4] = {0,0,0,0};
            u64 HE[4] = {0,0,0,0};
            float H12[4] = {0,0,0,0};
            #pragma unroll
            for (int k = 0; k < WS + 3; k++) {
                u64 mk = vM[base + cb + k];
                u64 ek = vE[base + cb + k];
                float tk = v12[base + cb + k];
                #pragma unroll
                for (int r = 0; r < 4; r++) {
                    int kk = k - r;
                    if (kk >= 0 && kk < WS) {
                        float w = gwc(kk);
                        u64 ww = pk2(w, w);
                        HM[r] = fma2(ww, mk, HM[r]);
                        HE[r] = fma2(ww, ek, HE[r]);
                        H12[r] = fmaf(w, tk, H12[r]);
                    }
                }
            }
            const float C1 = 1e-4f;
            const float C2 = 9e-4f;
            #pragma unroll
            for (int r = 0; r < 4; r++) {
                float mu1 = lo2(HM[r]);
                float mu2 = hi2(HM[r]);
                float e11 = lo2(HE[r]);
                float e22 = hi2(HE[r]);
                float mu1sq = mu1 * mu1;
                float mu2sq = mu2 * mu2;
                float mu12  = mu1 * mu2;
                float s11 = e11 - mu1sq;
                float s22 = e22 - mu2sq;
                float s12 = H12[r] - mu12;
                float numer = (2.f * mu12 + C1) * (2.f * s12 + C2);
                float denom = (mu1sq + mu2sq + C1) * (s11 + s22 + C2);
                float ssim = __fdividef(numer, denom);
                lnum += (1.f - ssim) * msk[ii][r];
            }
        }
        __syncthreads();
    }

    // =================== block reduction + partials + last-block finalize ========
    const unsigned full = 0xffffffffu;
    #pragma unroll
    for (int o = 16; o > 0; o >>= 1) {
        lnum += __shfl_down_sync(full, lnum, o);
        lden += __shfl_down_sync(full, lden, o);
    }
    __shared__ float red[16];
    __shared__ unsigned s_last;
    int wid = tid >> 5, lane = tid & 31;
    if (lane == 0) { red[wid] = lnum; red[wid + 8] = lden; }
    __syncthreads();
    if (tid == 0) {
        float n = 0.f, d = 0.f;
        #pragma unroll
        for (int i = 0; i < 8; i++) { n += red[i]; d += red[i + 8]; }
        int blk = (blockIdx.z * gridDim.y + blockIdx.y) * gridDim.x + blockIdx.x;
        g_pnum[blk] = n;
        g_pden[blk] = d;
        __threadfence();
        unsigned o = atomicAdd(&g_cnt, 1u);
        s_last = (o == NBLK - 1) ? 1u : 0u;
    }
    __syncthreads();

    if (s_last) {
        __threadfence();
        double dn = 0.0, dd = 0.0;
        for (int i = tid; i < NBLK; i += NTHREADS) {
            dn += (double)g_pnum[i];
            dd += (double)g_pden[i];
        }
        #pragma unroll
        for (int o = 16; o > 0; o >>= 1) {
            dn += __shfl_down_sync(full, dn, o);
            dd += __shfl_down_sync(full, dd, o);
        }
        __shared__ double dred[16];
        if (lane == 0) { dred[wid] = dn; dred[wid + 8] = dd; }
        __syncthreads();
        if (tid == 0) {
            double n = 0.0, d = 0.0;
            #pragma unroll
            for (int i = 0; i < 8; i++) { n += dred[i]; d += dred[i + 8]; }
            out[0] = (float)(n / d / 3.0);
            g_cnt = 0;   // reset for next graph replay
        }
    }
}

extern "C" void kernel_launch(void* const* d_in, const int* in_sizes, int n_in,
                              void* d_out, int out_size) {
    const float* img1  = (const float*)d_in[0];
    const float* img2  = (const float*)d_in[1];
    const float* match = (const float*)d_in[2];

    cudaFuncSetAttribute(ssim_kernel,
                         cudaFuncAttributeMaxDynamicSharedMemorySize, SMEM_BYTES);

    dim3 grid(W / TX, H / TY, BATCH);
    ssim_kernel<<<grid, NTHREADS, SMEM_BYTES>>>(img1, img2, match, (float*)d_out);
}

// round 5
// speedup vs baseline: 2.1365x; 1.1831x over previous
#include <cuda_runtime.h>
#include <math.h>

#define BATCH 16
#define CH    3
#define H     512
#define W     512
#define WS    11

#define TX    64
#define TY    32
#define TXW   (TX + 10)     // 74 plane columns
#define XPAD  80            // padded x iteration range for pass V
#define PITCH 75            // odd pitch -> conflict-free LDS
#define NTHREADS 256
#define NBLK  ((W/TX)*(H/TY)*BATCH)   // 2048

typedef unsigned long long u64;

#define W0 0.00102838f
#define W1 0.00759876f
#define W2 0.03600077f
#define W3 0.10936070f
#define W4 0.21300554f
#define W5 0.26601173f
__device__ __forceinline__ float gwc(int k) {
    const float t[WS] = {W0,W1,W2,W3,W4,W5,W4,W3,W2,W1,W0};
    return t[k];   // fully-unrolled callers -> compile-time constant
}

__device__ float    g_pnum[NBLK];
__device__ float    g_pden[NBLK];
__device__ unsigned g_cnt;

// ---------------- f32x2 packed helpers ----------------
__device__ __forceinline__ u64 pk2(float lo, float hi) {
    u64 r; asm("mov.b64 %0, {%1, %2};" : "=l"(r) : "f"(lo), "f"(hi)); return r;
}
__device__ __forceinline__ float lo2(u64 v) {
    float a, b; asm("mov.b64 {%0, %1}, %2;" : "=f"(a), "=f"(b) : "l"(v)); return a;
}
__device__ __forceinline__ float hi2(u64 v) {
    float a, b; asm("mov.b64 {%0, %1}, %2;" : "=f"(a), "=f"(b) : "l"(v)); return b;
}
__device__ __forceinline__ u64 mul2(u64 a, u64 b) {
    u64 d; asm("mul.rn.f32x2 %0, %1, %2;" : "=l"(d) : "l"(a), "l"(b)); return d;
}
__device__ __forceinline__ u64 fma2(u64 a, u64 b, u64 c) {
    u64 d; asm("fma.rn.f32x2 %0, %1, %2, %3;" : "=l"(d) : "l"(a), "l"(b), "l"(c)); return d;
}

extern __shared__ float smem[];

// smem layout (floats):
//   vM   : TY*PITCH u64 = 4800 floats   packed (mu1v, mu2v)
//   vE   : TY*PITCH u64 = 4800 floats   packed (E11v, E22v)
//   v12  : TY*PITCH     = 2400 floats   E12v  (also mask box scratch)
#define OFF_VM    0
#define OFF_VE    (TY*PITCH*2)
#define OFF_V12   (OFF_VE + TY*PITCH*2)
#define SMEM_FLOATS (OFF_V12 + TY*PITCH)
#define SMEM_BYTES  (SMEM_FLOATS * (int)sizeof(float))

// ---------------- pass V: vertical box filter on match (mask scratch) ---------
template<bool CHK>
__device__ __forceinline__ void mask_passV(const float* __restrict__ mp,
                                           int x0, int y0, float* v12, int tid) {
    for (int i = tid; i < XPAD * (TY / 4); i += NTHREADS) {
        int x  = i % XPAD;
        int yb = (i / XPAD) * 4;
        if (x >= TXW) continue;
        int gx = x0 + x - 5;
        float S[4] = {0, 0, 0, 0};
        if (CHK) {
            bool xin = (unsigned)gx < W;
            #pragma unroll
            for (int k = 0; k < WS + 3; k++) {
                int gy = y0 + yb + k - 5;
                float v = (xin && (unsigned)gy < H) ? mp[gy * W + gx] : 0.f;
                #pragma unroll
                for (int r = 0; r < 4; r++) {
                    int kk = k - r;
                    if (kk >= 0 && kk < WS) S[r] += v;
                }
            }
        } else {
            const float* col = mp + (size_t)(y0 + yb - 5) * W + gx;
            #pragma unroll
            for (int k = 0; k < WS + 3; k++) {
                float v = col[k * W];
                #pragma unroll
                for (int r = 0; r < 4; r++) {
                    int kk = k - r;
                    if (kk >= 0 && kk < WS) S[r] += v;
                }
            }
        }
        #pragma unroll
        for (int r = 0; r < 4; r++) v12[(yb + r) * PITCH + x] = S[r];
    }
}

// ---------------- pass V: vertical Gaussian on raw moments -------------------
template<bool CHK>
__device__ __forceinline__ void chan_passV(const float* __restrict__ p1,
                                           const float* __restrict__ p2,
                                           int x0, int y0,
                                           u64* vM, u64* vE, float* v12, int tid) {
    for (int i = tid; i < XPAD * (TY / 4); i += NTHREADS) {
        int x  = i % XPAD;
        int yb = (i / XPAD) * 4;
        if (x >= TXW) continue;
        int gx = x0 + x - 5;
        bool xin = (unsigned)gx < W;
        const float* c1 = p1 + (size_t)(y0 + yb - 5) * W + gx;
        const float* c2 = p2 + (size_t)(y0 + yb - 5) * W + gx;

        u64 VM[4] = {0,0,0,0};
        u64 VE[4] = {0,0,0,0};
        float V12[4] = {0,0,0,0};

        #pragma unroll
        for (int k = 0; k < WS + 3; k++) {
            float a, bb;
            if (CHK) {
                int gy = y0 + yb + k - 5;
                bool in = xin && (unsigned)gy < H;
                a  = in ? p1[gy * W + gx] : 0.f;
                bb = in ? p2[gy * W + gx] : 0.f;
            } else {
                a  = c1[k * W];
                bb = c2[k * W];
            }
            u64 v  = pk2(a, bb);
            u64 v2 = mul2(v, v);      // (a*a, b*b) once per load
            float p = a * bb;         // once per load
            #pragma unroll
            for (int r = 0; r < 4; r++) {
                int kk = k - r;
                if (kk >= 0 && kk < WS) {
                    float w = gwc(kk);
                    u64 ww = pk2(w, w);
                    VM[r]  = fma2(ww, v,  VM[r]);
                    VE[r]  = fma2(ww, v2, VE[r]);
                    V12[r] = fmaf(w, p, V12[r]);
                }
            }
        }
        #pragma unroll
        for (int r = 0; r < 4; r++) {
            int o = (yb + r) * PITCH + x;
            vM[o]  = VM[r];
            vE[o]  = VE[r];
            v12[o] = V12[r];
        }
    }
}

__global__ __launch_bounds__(NTHREADS, 4) void ssim_kernel(
    const float* __restrict__ img1,
    const float* __restrict__ img2,
    const float* __restrict__ match,
    float* __restrict__ out)
{
    u64*   vM  = (u64*)(smem + OFF_VM);
    u64*   vE  = (u64*)(smem + OFF_VE);
    float* v12 = smem + OFF_V12;

    const int tid = threadIdx.x;
    const int x0 = blockIdx.x * TX;
    const int y0 = blockIdx.y * TY;
    const int b  = blockIdx.z;
    const bool interior = (x0 > 0) && (x0 + TX < W) && (y0 > 0) && (y0 + TY < H);

    float lnum = 0.f;
    float lden = 0.f;
    float msk[2][4];

    // =================== mask phase (uses v12 plane as scratch) ===================
    {
        const float* mp = match + (size_t)b * H * W;
        if (interior) mask_passV<false>(mp, x0, y0, v12, tid);
        else          mask_passV<true >(mp, x0, y0, v12, tid);
        __syncthreads();
        #pragma unroll
        for (int ii = 0; ii < 2; ii++) {
            int i  = tid + ii * NTHREADS;
            int y  = i & 31;
            int xg = i >> 5;
            int base = y * PITCH + 4 * xg;
            float tb[WS + 3];
            #pragma unroll
            for (int k = 0; k < WS + 3; k++) tb[k] = v12[base + k];
            float S = 0.f;
            #pragma unroll
            for (int k = 0; k < WS; k++) S += tb[k];
            #pragma unroll
            for (int r = 0; r < 4; r++) {
                if (r > 0) S = S - tb[r - 1] + tb[r + WS - 1];
                float m = S * (1.0f / 121.0f) + 1e-07f;
                float mv = (m > 0.5f) ? (1.0f + 1e-07f) : 1e-07f;
                msk[ii][r] = mv;
                lden += mv;
            }
        }
        __syncthreads();
    }

    // =================== per-channel: pass V then pass H ===================
    for (int c = 0; c < CH; c++) {
        const float* p1 = img1 + ((size_t)b * CH + c) * H * W;
        const float* p2 = img2 + ((size_t)b * CH + c) * H * W;

        if (interior) chan_passV<false>(p1, p2, x0, y0, vM, vE, v12, tid);
        else          chan_passV<true >(p1, p2, x0, y0, vM, vE, v12, tid);
        __syncthreads();

        // ---- pass H: horizontal Gaussian + SSIM. lanes = y (conflict-free)
        #pragma unroll
        for (int ii = 0; ii < 2; ii++) {
            int i  = tid + ii * NTHREADS;
            int y  = i & 31;
            int xg = i >> 5;
            int base = y * PITCH + 4 * xg;

            u64 HM[4] = {0,0,0,0};
            u64 HE[4] = {0,0,0,0};
            float H12[4] = {0,0,0,0};
            #pragma unroll
            for (int k = 0; k < WS + 3; k++) {
                u64 mk  = vM[base + k];
                u64 ek  = vE[base + k];
                float tk = v12[base + k];
                #pragma unroll
                for (int r = 0; r < 4; r++) {
                    int kk = k - r;
                    if (kk >= 0 && kk < WS) {
                        float w = gwc(kk);
                        u64 ww = pk2(w, w);
                        HM[r]  = fma2(ww, mk, HM[r]);
                        HE[r]  = fma2(ww, ek, HE[r]);
                        H12[r] = fmaf(w, tk, H12[r]);
                    }
                }
            }
            const float C1 = 1e-4f;
            const float C2 = 9e-4f;
            #pragma unroll
            for (int r = 0; r < 4; r++) {
                float mu1 = lo2(HM[r]);
                float mu2 = hi2(HM[r]);
                float e11 = lo2(HE[r]);
                float e22 = hi2(HE[r]);
                float mu1sq = mu1 * mu1;
                float mu2sq = mu2 * mu2;
                float mu12  = mu1 * mu2;
                float s11 = e11 - mu1sq;
                float s22 = e22 - mu2sq;
                float s12 = H12[r] - mu12;
                float numer = (2.f * mu12 + C1) * (2.f * s12 + C2);
                float denom = (mu1sq + mu2sq + C1) * (s11 + s22 + C2);
                float ssim = __fdividef(numer, denom);
                lnum += (1.f - ssim) * msk[ii][r];
            }
        }
        __syncthreads();
    }

    // =================== block reduction + partials + last-block finalize ========
    const unsigned full = 0xffffffffu;
    #pragma unroll
    for (int o = 16; o > 0; o >>= 1) {
        lnum += __shfl_down_sync(full, lnum, o);
        lden += __shfl_down_sync(full, lden, o);
    }
    __shared__ float red[16];
    __shared__ unsigned s_last;
    int wid = tid >> 5, lane = tid & 31;
    if (lane == 0) { red[wid] = lnum; red[wid + 8] = lden; }
    __syncthreads();
    if (tid == 0) {
        float n = 0.f, d = 0.f;
        #pragma unroll
        for (int i = 0; i < 8; i++) { n += red[i]; d += red[i + 8]; }
        int blk = (blockIdx.z * gridDim.y + blockIdx.y) * gridDim.x + blockIdx.x;
        g_pnum[blk] = n;
        g_pden[blk] = d;
        __threadfence();
        unsigned o = atomicAdd(&g_cnt, 1u);
        s_last = (o == NBLK - 1) ? 1u : 0u;
    }
    __syncthreads();

    if (s_last) {
        __threadfence();
        double dn = 0.0, dd = 0.0;
        for (int i = tid; i < NBLK; i += NTHREADS) {
            dn += (double)g_pnum[i];
            dd += (double)g_pden[i];
        }
        #pragma unroll
        for (int o = 16; o > 0; o >>= 1) {
            dn += __shfl_down_sync(full, dn, o);
            dd += __shfl_down_sync(full, dd, o);
        }
        __shared__ double dred[16];
        if (lane == 0) { dred[wid] = dn; dred[wid + 8] = dd; }
        __syncthreads();
        if (tid == 0) {
            double n = 0.0, d = 0.0;
            #pragma unroll
            for (int i = 0; i < 8; i++) { n += dred[i]; d += dred[i + 8]; }
            out[0] = (float)(n / d / 3.0);
            g_cnt = 0;   // reset for next graph replay
        }
    }
}

extern "C" void kernel_launch(void* const* d_in, const int* in_sizes, int n_in,
                              void* d_out, int out_size) {
    const float* img1  = (const float*)d_in[0];
    const float* img2  = (const float*)d_in[1];
    const float* match = (const float*)d_in[2];

    cudaFuncSetAttribute(ssim_kernel,
                         cudaFuncAttributeMaxDynamicSharedMemorySize, SMEM_BYTES);

    dim3 grid(W / TX, H / TY, BATCH);
    ssim_kernel<<<grid, NTHREADS, SMEM_BYTES>>>(img1, img2, match, (float*)d_out);
}